// round 3
// baseline (speedup 1.0000x reference)
#include <cuda_runtime.h>
#include <cuda_bf16.h>

#define NNODES 50000
#define NEDGES 800000
#define DIM    128

// -------- scratch (static device globals; no allocation) --------
__device__ float g_H[NNODES * DIM];     // hidden state between layers
__device__ float g_AGG[NNODES * DIM];   // SpMM output
__device__ int   g_deg_in[NNODES];
__device__ int   g_deg_out[NNODES];
__device__ float g_norm_src[NNODES];
__device__ float g_norm_dst[NNODES];
__device__ int   g_rowptr[NNODES + 1];
__device__ int   g_fill[NNODES];
__device__ int   g_csr_src[NEDGES];

// ---------------- build kernels ----------------
__global__ void zero_counts() {
    int i = blockIdx.x * blockDim.x + threadIdx.x;
    if (i < NNODES) { g_deg_in[i] = 0; g_deg_out[i] = 0; g_fill[i] = 0; }
}

__global__ void hist_kernel(const int* __restrict__ src, const int* __restrict__ dst) {
    int e = blockIdx.x * blockDim.x + threadIdx.x;
    if (e < NEDGES) {
        atomicAdd(&g_deg_out[src[e]], 1);
        atomicAdd(&g_deg_in[dst[e]], 1);
    }
}

__global__ void norm_kernel() {
    int i = blockIdx.x * blockDim.x + threadIdx.x;
    if (i < NNODES) {
        g_norm_src[i] = rsqrtf((float)max(g_deg_out[i], 1));
        g_norm_dst[i] = rsqrtf((float)max(g_deg_in[i], 1));
    }
}

// single-block exclusive scan of g_deg_in -> g_rowptr (N=50000, 1024 threads)
__global__ void scan_kernel() {
    __shared__ int sums[1024];
    const int CH = (NNODES + 1023) / 1024;  // 49
    int t = threadIdx.x;
    int base = t * CH;
    int s = 0;
    for (int i = 0; i < CH; i++) {
        int idx = base + i;
        if (idx < NNODES) s += g_deg_in[idx];
    }
    sums[t] = s;
    __syncthreads();
    for (int off = 1; off < 1024; off <<= 1) {
        int add = 0;
        if (t >= off) add = sums[t - off];
        __syncthreads();
        sums[t] += add;
        __syncthreads();
    }
    int run = (t > 0) ? sums[t - 1] : 0;
    for (int i = 0; i < CH; i++) {
        int idx = base + i;
        if (idx < NNODES) { g_rowptr[idx] = run; run += g_deg_in[idx]; }
    }
    if (t == 1023) g_rowptr[NNODES] = run;  // == NEDGES
}

__global__ void fill_kernel(const int* __restrict__ src, const int* __restrict__ dst) {
    int e = blockIdx.x * blockDim.x + threadIdx.x;
    if (e < NEDGES) {
        int d = dst[e];
        int p = atomicAdd(&g_fill[d], 1);
        g_csr_src[g_rowptr[d] + p] = src[e];
    }
}

// ---------------- embedding gather ----------------
// one warp per node; lane handles 4 floats (float4)
__global__ void embed_kernel(const int* __restrict__ batch, const float* __restrict__ emb) {
    int gid = blockIdx.x * blockDim.x + threadIdx.x;
    int n = gid >> 5;
    int lane = gid & 31;
    if (n >= NNODES) return;
    int b = __ldg(&batch[n]);
    float4 v = *(const float4*)&emb[(size_t)b * DIM + lane * 4];
    *(float4*)&g_H[(size_t)n * DIM + lane * 4] = v;
}

// ---------------- SpMM: AGG[i] = norm_dst[i] * sum_{j in N(i)} norm_src[j] * H[j] ----------------
// one warp per destination node
__global__ void spmm_kernel(const float* __restrict__ Hin) {
    int gid = blockIdx.x * blockDim.x + threadIdx.x;
    int n = gid >> 5;
    int lane = gid & 31;
    if (n >= NNODES) return;
    int beg = __ldg(&g_rowptr[n]);
    int end = __ldg(&g_rowptr[n + 1]);
    float4 acc = make_float4(0.f, 0.f, 0.f, 0.f);
    for (int e = beg; e < end; e++) {
        int s = __ldg(&g_csr_src[e]);
        float ns = __ldg(&g_norm_src[s]);
        float4 v = *(const float4*)&Hin[(size_t)s * DIM + lane * 4];
        acc.x += ns * v.x;
        acc.y += ns * v.y;
        acc.z += ns * v.z;
        acc.w += ns * v.w;
    }
    float nd = __ldg(&g_norm_dst[n]);
    acc.x *= nd; acc.y *= nd; acc.z *= nd; acc.w *= nd;
    *(float4*)&g_AGG[(size_t)n * DIM + lane * 4] = acc;
}

// ---------------- GEMM: out = relu(A @ W + b), A:[M,128], W:[128,128] ----------------
// block computes 128x128 tile; 256 threads, 8x8 micro-tile each; KC=32 smem chunks
__global__ __launch_bounds__(256, 2) void gemm_bias_relu(
    const float* __restrict__ A, const float* __restrict__ W,
    const float* __restrict__ bias, float* __restrict__ out, int M)
{
    const int KC = 32;
    __shared__ float As[KC][132];   // transposed: As[k][m], padded
    __shared__ float Ws[KC][128];

    int tid = threadIdx.x;
    int tx = tid & 15, ty = tid >> 4;
    int rm = ty * 8, cn = tx * 8;
    int row0 = blockIdx.x * 128;

    float acc[8][8];
    #pragma unroll
    for (int i = 0; i < 8; i++)
        #pragma unroll
        for (int j = 0; j < 8; j++) acc[i][j] = 0.f;

    int lrow = tid >> 3;   // 0..31
    int lf4  = tid & 7;    // 0..7 (float4 index along 32-wide K chunk)

    for (int k0 = 0; k0 < 128; k0 += KC) {
        // load A chunk (128 rows x 32 k), store transposed
        #pragma unroll
        for (int rp = 0; rp < 4; rp++) {
            int r = lrow + rp * 32;
            int grow = row0 + r;
            float4 v = make_float4(0.f, 0.f, 0.f, 0.f);
            if (grow < M) v = *(const float4*)&A[(size_t)grow * 128 + k0 + lf4 * 4];
            As[lf4 * 4 + 0][r] = v.x;
            As[lf4 * 4 + 1][r] = v.y;
            As[lf4 * 4 + 2][r] = v.z;
            As[lf4 * 4 + 3][r] = v.w;
        }
        // load W chunk (32 x 128)
        #pragma unroll
        for (int wp = 0; wp < 4; wp++) {
            int idx = tid + wp * 256;     // float4 index 0..1023
            int kk = idx >> 5;            // 128/4 = 32 float4 per row
            int c4 = idx & 31;
            float4 w = *(const float4*)&W[(size_t)(k0 + kk) * 128 + c4 * 4];
            *(float4*)&Ws[kk][c4 * 4] = w;
        }
        __syncthreads();

        #pragma unroll
        for (int kk = 0; kk < KC; kk++) {
            float a[8], w[8];
            *(float4*)&a[0] = *(const float4*)&As[kk][rm];
            *(float4*)&a[4] = *(const float4*)&As[kk][rm + 4];
            *(float4*)&w[0] = *(const float4*)&Ws[kk][cn];
            *(float4*)&w[4] = *(const float4*)&Ws[kk][cn + 4];
            #pragma unroll
            for (int i = 0; i < 8; i++)
                #pragma unroll
                for (int j = 0; j < 8; j++)
                    acc[i][j] += a[i] * w[j];
        }
        __syncthreads();
    }

    float bv[8];
    *(float4*)&bv[0] = *(const float4*)&bias[cn];
    *(float4*)&bv[4] = *(const float4*)&bias[cn + 4];

    #pragma unroll
    for (int i = 0; i < 8; i++) {
        int grow = row0 + rm + i;
        if (grow < M) {
            float4 o0, o1;
            o0.x = fmaxf(acc[i][0] + bv[0], 0.f);
            o0.y = fmaxf(acc[i][1] + bv[1], 0.f);
            o0.z = fmaxf(acc[i][2] + bv[2], 0.f);
            o0.w = fmaxf(acc[i][3] + bv[3], 0.f);
            o1.x = fmaxf(acc[i][4] + bv[4], 0.f);
            o1.y = fmaxf(acc[i][5] + bv[5], 0.f);
            o1.z = fmaxf(acc[i][6] + bv[6], 0.f);
            o1.w = fmaxf(acc[i][7] + bv[7], 0.f);
            *(float4*)&out[(size_t)grow * 128 + cn] = o0;
            *(float4*)&out[(size_t)grow * 128 + cn + 4] = o1;
        }
    }
}

// ---------------- launcher ----------------
extern "C" void kernel_launch(void* const* d_in, const int* in_sizes, int n_in,
                              void* d_out, int out_size) {
    const int*   batch = (const int*)d_in[0];
    const int*   src   = (const int*)d_in[1];
    const int*   dst   = (const int*)d_in[2];
    const float* emb   = (const float*)d_in[3];
    const float* W1    = (const float*)d_in[4];
    const float* b1    = (const float*)d_in[5];
    const float* W2    = (const float*)d_in[6];
    const float* b2    = (const float*)d_in[7];
    const float* W3    = (const float*)d_in[8];
    const float* b3    = (const float*)d_in[9];
    float* out = (float*)d_out;

    float* H;   cudaGetSymbolAddress((void**)&H,   g_H);
    float* AGG; cudaGetSymbolAddress((void**)&AGG, g_AGG);

    const int TB = 256;
    // build CSR + norms
    zero_counts<<<(NNODES + TB - 1) / TB, TB>>>();
    hist_kernel<<<(NEDGES + TB - 1) / TB, TB>>>(src, dst);
    norm_kernel<<<(NNODES + TB - 1) / TB, TB>>>();
    scan_kernel<<<1, 1024>>>();
    fill_kernel<<<(NEDGES + TB - 1) / TB, TB>>>(src, dst);

    // embedding gather
    embed_kernel<<<(NNODES * 32 + TB - 1) / TB, TB>>>(batch, emb);

    int spmm_blocks = (NNODES * 32 + TB - 1) / TB;
    int gemm_blocks = (NNODES + 127) / 128;

    // layer 1
    spmm_kernel<<<spmm_blocks, TB>>>(H);
    gemm_bias_relu<<<gemm_blocks, 256>>>(AGG, W1, b1, H, NNODES);
    // layer 2
    spmm_kernel<<<spmm_blocks, TB>>>(H);
    gemm_bias_relu<<<gemm_blocks, 256>>>(AGG, W2, b2, H, NNODES);
    // layer 3
    spmm_kernel<<<spmm_blocks, TB>>>(H);
    gemm_bias_relu<<<gemm_blocks, 256>>>(AGG, W3, b3, out, NNODES);
}

// round 6
// speedup vs baseline: 1.1888x; 1.1888x over previous
#include <cuda_runtime.h>
#include <cuda_bf16.h>

#define NNODES 50000
#define NEDGES 800000
#define DIM    128
#define NBLK_SCAN ((NNODES + 255) / 256)   // 196

// -------- scratch (static device globals; no allocation) --------
__device__ float g_H[NNODES * DIM];     // hidden state between layers (pre-scaled by norm_src for layers feeding SpMM)
__device__ float g_AGG[NNODES * DIM];   // SpMM output
__device__ int   g_deg_in[NNODES];
__device__ int   g_deg_out[NNODES];
__device__ float g_norm_src[NNODES];
__device__ float g_norm_dst[NNODES];
__device__ int   g_rowptr[NNODES + 1];
__device__ int   g_fill[NNODES];
__device__ int   g_csr_src[NEDGES];
__device__ int   g_bsum[256];
__device__ int   g_boff[256];

// ---------------- build kernels ----------------
__global__ void zero_counts() {
    int i = blockIdx.x * blockDim.x + threadIdx.x;
    if (i < NNODES) { g_deg_in[i] = 0; g_deg_out[i] = 0; g_fill[i] = 0; }
}

__global__ void hist_kernel(const int* __restrict__ src, const int* __restrict__ dst) {
    int e = blockIdx.x * blockDim.x + threadIdx.x;
    if (e < NEDGES) {
        atomicAdd(&g_deg_out[src[e]], 1);
        atomicAdd(&g_deg_in[dst[e]], 1);
    }
}

__global__ void norm_kernel() {
    int i = blockIdx.x * blockDim.x + threadIdx.x;
    if (i < NNODES) {
        g_norm_src[i] = rsqrtf((float)max(g_deg_out[i], 1));
        g_norm_dst[i] = rsqrtf((float)max(g_deg_in[i], 1));
    }
}

// ---- coalesced 3-phase exclusive scan of g_deg_in -> g_rowptr ----
__global__ void deg_partial() {
    __shared__ int sdata[256];
    int t = threadIdx.x;
    int idx = blockIdx.x * 256 + t;
    int v = (idx < NNODES) ? g_deg_in[idx] : 0;
    sdata[t] = v;
    __syncthreads();
    for (int off = 128; off > 0; off >>= 1) {
        if (t < off) sdata[t] += sdata[t + off];
        __syncthreads();
    }
    if (t == 0) g_bsum[blockIdx.x] = sdata[0];
}

__global__ void scan_bsums() {
    __shared__ int s[256];
    int t = threadIdx.x;
    int v = (t < NBLK_SCAN) ? g_bsum[t] : 0;
    s[t] = v;
    __syncthreads();
    for (int off = 1; off < 256; off <<= 1) {
        int add = (t >= off) ? s[t - off] : 0;
        __syncthreads();
        s[t] += add;
        __syncthreads();
    }
    g_boff[t] = s[t] - v;   // exclusive
    if (t == 0) g_rowptr[NNODES] = NEDGES;
}

__global__ void scan_apply() {
    __shared__ int s[256];
    int t = threadIdx.x;
    int idx = blockIdx.x * 256 + t;
    int v = (idx < NNODES) ? g_deg_in[idx] : 0;
    s[t] = v;
    __syncthreads();
    for (int off = 1; off < 256; off <<= 1) {
        int add = (t >= off) ? s[t - off] : 0;
        __syncthreads();
        s[t] += add;
        __syncthreads();
    }
    if (idx < NNODES) g_rowptr[idx] = s[t] - v + g_boff[blockIdx.x];
}

__global__ void fill_kernel(const int* __restrict__ src, const int* __restrict__ dst) {
    int e = blockIdx.x * blockDim.x + threadIdx.x;
    if (e < NEDGES) {
        int d = dst[e];
        int p = atomicAdd(&g_fill[d], 1);
        g_csr_src[g_rowptr[d] + p] = src[e];
    }
}

// ---------------- embedding gather (pre-scaled by norm_src) ----------------
__global__ void embed_kernel(const int* __restrict__ batch, const float* __restrict__ emb) {
    int gid = blockIdx.x * blockDim.x + threadIdx.x;
    int n = gid >> 5;
    int lane = gid & 31;
    if (n >= NNODES) return;
    int b = __ldg(&batch[n]);
    float ns = __ldg(&g_norm_src[n]);
    float4 v = *(const float4*)&emb[(size_t)b * DIM + lane * 4];
    v.x *= ns; v.y *= ns; v.z *= ns; v.w *= ns;
    *(float4*)&g_H[(size_t)n * DIM + lane * 4] = v;
}

// ---------------- SpMM: AGG[i] = norm_dst[i] * sum_{j in N(i)} Hs[j] ----------------
// Hs rows already pre-scaled by norm_src. One warp per destination node, edge loop unrolled x4.
__global__ void spmm_kernel(const float* __restrict__ Hs) {
    int gid = blockIdx.x * blockDim.x + threadIdx.x;
    int n = gid >> 5;
    int lane = gid & 31;
    if (n >= NNODES) return;
    int beg = __ldg(&g_rowptr[n]);
    int end = __ldg(&g_rowptr[n + 1]);
    float4 a0 = make_float4(0.f, 0.f, 0.f, 0.f);
    float4 a1 = make_float4(0.f, 0.f, 0.f, 0.f);
    float4 a2 = make_float4(0.f, 0.f, 0.f, 0.f);
    float4 a3 = make_float4(0.f, 0.f, 0.f, 0.f);
    int e = beg;
    int off = lane * 4;
    for (; e + 4 <= end; e += 4) {
        int s0 = __ldg(&g_csr_src[e]);
        int s1 = __ldg(&g_csr_src[e + 1]);
        int s2 = __ldg(&g_csr_src[e + 2]);
        int s3 = __ldg(&g_csr_src[e + 3]);
        float4 v0 = *(const float4*)&Hs[(size_t)s0 * DIM + off];
        float4 v1 = *(const float4*)&Hs[(size_t)s1 * DIM + off];
        float4 v2 = *(const float4*)&Hs[(size_t)s2 * DIM + off];
        float4 v3 = *(const float4*)&Hs[(size_t)s3 * DIM + off];
        a0.x += v0.x; a0.y += v0.y; a0.z += v0.z; a0.w += v0.w;
        a1.x += v1.x; a1.y += v1.y; a1.z += v1.z; a1.w += v1.w;
        a2.x += v2.x; a2.y += v2.y; a2.z += v2.z; a2.w += v2.w;
        a3.x += v3.x; a3.y += v3.y; a3.z += v3.z; a3.w += v3.w;
    }
    for (; e < end; e++) {
        int s0 = __ldg(&g_csr_src[e]);
        float4 v0 = *(const float4*)&Hs[(size_t)s0 * DIM + off];
        a0.x += v0.x; a0.y += v0.y; a0.z += v0.z; a0.w += v0.w;
    }
    a0.x += a1.x + a2.x + a3.x;
    a0.y += a1.y + a2.y + a3.y;
    a0.z += a1.z + a2.z + a3.z;
    a0.w += a1.w + a2.w + a3.w;
    float nd = __ldg(&g_norm_dst[n]);
    a0.x *= nd; a0.y *= nd; a0.z *= nd; a0.w *= nd;
    *(float4*)&g_AGG[(size_t)n * DIM + off] = a0;
}

// ---------------- GEMM: out = relu(A @ W + b) [* rowscale], A:[M,128], W:[128,128] ----------------
__global__ __launch_bounds__(256, 2) void gemm_bias_relu(
    const float* __restrict__ A, const float* __restrict__ W,
    const float* __restrict__ bias, float* __restrict__ out, int M,
    const float* __restrict__ rowscale)
{
    const int KC = 32;
    __shared__ float As[KC][132];   // transposed: As[k][m], padded
    __shared__ float Ws[KC][128];

    int tid = threadIdx.x;
    int tx = tid & 15, ty = tid >> 4;
    int rm = ty * 8, cn = tx * 8;
    int row0 = blockIdx.x * 128;

    float acc[8][8];
    #pragma unroll
    for (int i = 0; i < 8; i++)
        #pragma unroll
        for (int j = 0; j < 8; j++) acc[i][j] = 0.f;

    int lrow = tid >> 3;   // 0..31
    int lf4  = tid & 7;    // 0..7

    for (int k0 = 0; k0 < 128; k0 += KC) {
        #pragma unroll
        for (int rp = 0; rp < 4; rp++) {
            int r = lrow + rp * 32;
            int grow = row0 + r;
            float4 v = make_float4(0.f, 0.f, 0.f, 0.f);
            if (grow < M) v = *(const float4*)&A[(size_t)grow * 128 + k0 + lf4 * 4];
            As[lf4 * 4 + 0][r] = v.x;
            As[lf4 * 4 + 1][r] = v.y;
            As[lf4 * 4 + 2][r] = v.z;
            As[lf4 * 4 + 3][r] = v.w;
        }
        #pragma unroll
        for (int wp = 0; wp < 4; wp++) {
            int idx = tid + wp * 256;
            int kk = idx >> 5;
            int c4 = idx & 31;
            float4 w = *(const float4*)&W[(size_t)(k0 + kk) * 128 + c4 * 4];
            *(float4*)&Ws[kk][c4 * 4] = w;
        }
        __syncthreads();

        #pragma unroll
        for (int kk = 0; kk < KC; kk++) {
            float a[8], w[8];
            *(float4*)&a[0] = *(const float4*)&As[kk][rm];
            *(float4*)&a[4] = *(const float4*)&As[kk][rm + 4];
            *(float4*)&w[0] = *(const float4*)&Ws[kk][cn];
            *(float4*)&w[4] = *(const float4*)&Ws[kk][cn + 4];
            #pragma unroll
            for (int i = 0; i < 8; i++)
                #pragma unroll
                for (int j = 0; j < 8; j++)
                    acc[i][j] += a[i] * w[j];
        }
        __syncthreads();
    }

    float bv[8];
    *(float4*)&bv[0] = *(const float4*)&bias[cn];
    *(float4*)&bv[4] = *(const float4*)&bias[cn + 4];

    #pragma unroll
    for (int i = 0; i < 8; i++) {
        int grow = row0 + rm + i;
        if (grow < M) {
            float s = rowscale ? __ldg(&rowscale[grow]) : 1.0f;
            float4 o0, o1;
            o0.x = fmaxf(acc[i][0] + bv[0], 0.f) * s;
            o0.y = fmaxf(acc[i][1] + bv[1], 0.f) * s;
            o0.z = fmaxf(acc[i][2] + bv[2], 0.f) * s;
            o0.w = fmaxf(acc[i][3] + bv[3], 0.f) * s;
            o1.x = fmaxf(acc[i][4] + bv[4], 0.f) * s;
            o1.y = fmaxf(acc[i][5] + bv[5], 0.f) * s;
            o1.z = fmaxf(acc[i][6] + bv[6], 0.f) * s;
            o1.w = fmaxf(acc[i][7] + bv[7], 0.f) * s;
            *(float4*)&out[(size_t)grow * 128 + cn] = o0;
            *(float4*)&out[(size_t)grow * 128 + cn + 4] = o1;
        }
    }
}

// ---------------- launcher ----------------
extern "C" void kernel_launch(void* const* d_in, const int* in_sizes, int n_in,
                              void* d_out, int out_size) {
    const int*   batch = (const int*)d_in[0];
    const int*   src   = (const int*)d_in[1];
    const int*   dst   = (const int*)d_in[2];
    const float* emb   = (const float*)d_in[3];
    const float* W1    = (const float*)d_in[4];
    const float* b1    = (const float*)d_in[5];
    const float* W2    = (const float*)d_in[6];
    const float* b2    = (const float*)d_in[7];
    const float* W3    = (const float*)d_in[8];
    const float* b3    = (const float*)d_in[9];
    float* out = (float*)d_out;

    float* H;   cudaGetSymbolAddress((void**)&H,   g_H);
    float* AGG; cudaGetSymbolAddress((void**)&AGG, g_AGG);
    float* NSRC; cudaGetSymbolAddress((void**)&NSRC, g_norm_src);

    const int TB = 256;
    // build CSR + norms
    zero_counts<<<(NNODES + TB - 1) / TB, TB>>>();
    hist_kernel<<<(NEDGES + TB - 1) / TB, TB>>>(src, dst);
    norm_kernel<<<(NNODES + TB - 1) / TB, TB>>>();
    deg_partial<<<NBLK_SCAN, 256>>>();
    scan_bsums<<<1, 256>>>();
    scan_apply<<<NBLK_SCAN, 256>>>();
    fill_kernel<<<(NEDGES + TB - 1) / TB, TB>>>(src, dst);

    // embedding gather (pre-scaled by norm_src)
    embed_kernel<<<(NNODES * 32 + TB - 1) / TB, TB>>>(batch, emb);

    int spmm_blocks = (NNODES * 32 + TB - 1) / TB;
    int gemm_blocks = (NNODES + 127) / 128;

    // layer 1  (H pre-scaled; gemm output pre-scaled for next spmm)
    spmm_kernel<<<spmm_blocks, TB>>>(H);
    gemm_bias_relu<<<gemm_blocks, 256>>>(AGG, W1, b1, H, NNODES, NSRC);
    // layer 2
    spmm_kernel<<<spmm_blocks, TB>>>(H);
    gemm_bias_relu<<<gemm_blocks, 256>>>(AGG, W2, b2, H, NNODES, NSRC);
    // layer 3 (final: no rowscale)
    spmm_kernel<<<spmm_blocks, TB>>>(H);
    gemm_bias_relu<<<gemm_blocks, 256>>>(AGG, W3, b3, out, NNODES, nullptr);
}

// round 11
// speedup vs baseline: 1.5523x; 1.3058x over previous
#include <cuda_runtime.h>
#include <cuda_bf16.h>

#define NNODES 50000
#define NEDGES 800000
#define DIM    128
#define NBLK_SCAN ((NNODES + 255) / 256)   // 196

// -------- scratch (static device globals; no allocation) --------
__device__ float g_H[NNODES * DIM];
__device__ float g_AGG[NNODES * DIM];
__device__ int   g_deg_in[NNODES];
__device__ int   g_deg_out[NNODES];
__device__ float g_norm_src[NNODES];
__device__ float g_norm_dst[NNODES];
__device__ int   g_rowptr[NNODES + 1];
__device__ int   g_fill[NNODES];
__device__ int   g_csr_src[NEDGES];
__device__ int   g_bsum[256];
__device__ int   g_boff[256];

// ---------------- build kernels ----------------
__global__ void zero_counts() {
    int i = blockIdx.x * blockDim.x + threadIdx.x;
    if (i < NNODES) { g_deg_in[i] = 0; g_deg_out[i] = 0; g_fill[i] = 0; }
}

__global__ void hist_kernel(const int* __restrict__ src, const int* __restrict__ dst) {
    int e = blockIdx.x * blockDim.x + threadIdx.x;
    if (e < NEDGES) {
        atomicAdd(&g_deg_out[src[e]], 1);
        atomicAdd(&g_deg_in[dst[e]], 1);
    }
}

__global__ void norm_kernel() {
    int i = blockIdx.x * blockDim.x + threadIdx.x;
    if (i < NNODES) {
        g_norm_src[i] = rsqrtf((float)max(g_deg_out[i], 1));
        g_norm_dst[i] = rsqrtf((float)max(g_deg_in[i], 1));
    }
}

// ---- coalesced 3-phase exclusive scan of g_deg_in -> g_rowptr ----
__global__ void deg_partial() {
    __shared__ int sdata[256];
    int t = threadIdx.x;
    int idx = blockIdx.x * 256 + t;
    int v = (idx < NNODES) ? g_deg_in[idx] : 0;
    sdata[t] = v;
    __syncthreads();
    for (int off = 128; off > 0; off >>= 1) {
        if (t < off) sdata[t] += sdata[t + off];
        __syncthreads();
    }
    if (t == 0) g_bsum[blockIdx.x] = sdata[0];
}

__global__ void scan_bsums() {
    __shared__ int s[256];
    int t = threadIdx.x;
    int v = (t < NBLK_SCAN) ? g_bsum[t] : 0;
    s[t] = v;
    __syncthreads();
    for (int off = 1; off < 256; off <<= 1) {
        int add = (t >= off) ? s[t - off] : 0;
        __syncthreads();
        s[t] += add;
        __syncthreads();
    }
    g_boff[t] = s[t] - v;   // exclusive
    if (t == 0) g_rowptr[NNODES] = NEDGES;
}

__global__ void scan_apply() {
    __shared__ int s[256];
    int t = threadIdx.x;
    int idx = blockIdx.x * 256 + t;
    int v = (idx < NNODES) ? g_deg_in[idx] : 0;
    s[t] = v;
    __syncthreads();
    for (int off = 1; off < 256; off <<= 1) {
        int add = (t >= off) ? s[t - off] : 0;
        __syncthreads();
        s[t] += add;
        __syncthreads();
    }
    if (idx < NNODES) g_rowptr[idx] = s[t] - v + g_boff[blockIdx.x];
}

__global__ void fill_kernel(const int* __restrict__ src, const int* __restrict__ dst) {
    int e = blockIdx.x * blockDim.x + threadIdx.x;
    if (e < NEDGES) {
        int d = dst[e];
        int p = atomicAdd(&g_fill[d], 1);
        g_csr_src[g_rowptr[d] + p] = src[e];
    }
}

// ---------------- embedding gather (pre-scaled by norm_src) ----------------
__global__ void embed_kernel(const int* __restrict__ batch, const float* __restrict__ emb) {
    int gid = blockIdx.x * blockDim.x + threadIdx.x;
    int n = gid >> 5;
    int lane = gid & 31;
    if (n >= NNODES) return;
    int b = __ldg(&batch[n]);
    float ns = __ldg(&g_norm_src[n]);
    float4 v = *(const float4*)&emb[(size_t)b * DIM + lane * 4];
    v.x *= ns; v.y *= ns; v.z *= ns; v.w *= ns;
    *(float4*)&g_H[(size_t)n * DIM + lane * 4] = v;
}

// ---------------- SpMM: AGG[i] = norm_dst[i] * sum_{j in N(i)} Hs[j] ----------------
__global__ void spmm_kernel(const float* __restrict__ Hs) {
    int gid = blockIdx.x * blockDim.x + threadIdx.x;
    int n = gid >> 5;
    int lane = gid & 31;
    if (n >= NNODES) return;
    int beg = __ldg(&g_rowptr[n]);
    int end = __ldg(&g_rowptr[n + 1]);
    float4 a0 = make_float4(0.f, 0.f, 0.f, 0.f);
    float4 a1 = make_float4(0.f, 0.f, 0.f, 0.f);
    float4 a2 = make_float4(0.f, 0.f, 0.f, 0.f);
    float4 a3 = make_float4(0.f, 0.f, 0.f, 0.f);
    int e = beg;
    int off = lane * 4;
    for (; e + 4 <= end; e += 4) {
        int s0 = __ldg(&g_csr_src[e]);
        int s1 = __ldg(&g_csr_src[e + 1]);
        int s2 = __ldg(&g_csr_src[e + 2]);
        int s3 = __ldg(&g_csr_src[e + 3]);
        float4 v0 = *(const float4*)&Hs[(size_t)s0 * DIM + off];
        float4 v1 = *(const float4*)&Hs[(size_t)s1 * DIM + off];
        float4 v2 = *(const float4*)&Hs[(size_t)s2 * DIM + off];
        float4 v3 = *(const float4*)&Hs[(size_t)s3 * DIM + off];
        a0.x += v0.x; a0.y += v0.y; a0.z += v0.z; a0.w += v0.w;
        a1.x += v1.x; a1.y += v1.y; a1.z += v1.z; a1.w += v1.w;
        a2.x += v2.x; a2.y += v2.y; a2.z += v2.z; a2.w += v2.w;
        a3.x += v3.x; a3.y += v3.y; a3.z += v3.z; a3.w += v3.w;
    }
    for (; e < end; e++) {
        int s0 = __ldg(&g_csr_src[e]);
        float4 v0 = *(const float4*)&Hs[(size_t)s0 * DIM + off];
        a0.x += v0.x; a0.y += v0.y; a0.z += v0.z; a0.w += v0.w;
    }
    a0.x += a1.x + a2.x + a3.x;
    a0.y += a1.y + a2.y + a3.y;
    a0.z += a1.z + a2.z + a3.z;
    a0.w += a1.w + a2.w + a3.w;
    float nd = __ldg(&g_norm_dst[n]);
    a0.x *= nd; a0.y *= nd; a0.z *= nd; a0.w *= nd;
    *(float4*)&g_AGG[(size_t)n * DIM + off] = a0;
}

// ---------------- tf32 tensor-core GEMM: out = relu(A @ W + b) [* rowscale] ----------------
__device__ __forceinline__ unsigned f2tf32(float x) {
    unsigned r;
    asm("cvt.rna.tf32.f32 %0, %1;" : "=r"(r) : "f"(x));
    return r;
}

__global__ __launch_bounds__(256, 2) void gemm_tf32(
    const float* __restrict__ A, const float* __restrict__ W,
    const float* __restrict__ bias, float* __restrict__ out, int M,
    const float* __restrict__ rowscale)
{
    const int KC = 32;
    __shared__ unsigned As[KC][132];   // transposed [k][m], tf32 bits
    __shared__ unsigned Ws[KC][132];   // [k][n], tf32 bits

    int tid = threadIdx.x;
    int wid = tid >> 5, lane = tid & 31;
    int g = lane >> 2, tg = lane & 3;          // quad layout
    int wm = (wid & 3) * 32;                   // warp M offset (4 warps down M)
    int wn = (wid >> 2) * 64;                  // warp N offset (2 warps across N)
    int row0 = blockIdx.x * 128;

    float acc[2][8][4];
    #pragma unroll
    for (int mf = 0; mf < 2; mf++)
        #pragma unroll
        for (int nf = 0; nf < 8; nf++)
            #pragma unroll
            for (int c = 0; c < 4; c++) acc[mf][nf][c] = 0.f;

    int lrow = tid >> 3;   // 0..31 (A row within 32-row group)
    int lf4  = tid & 7;    // 0..7  (float4 index along 32-wide K chunk)

    for (int k0 = 0; k0 < 128; k0 += KC) {
        // load A chunk (128 rows x 32 k), cvt tf32, store transposed
        #pragma unroll
        for (int rp = 0; rp < 4; rp++) {
            int r = lrow + rp * 32;
            int grow = row0 + r;
            float4 v = make_float4(0.f, 0.f, 0.f, 0.f);
            if (grow < M) v = *(const float4*)&A[(size_t)grow * 128 + k0 + lf4 * 4];
            As[lf4 * 4 + 0][r] = f2tf32(v.x);
            As[lf4 * 4 + 1][r] = f2tf32(v.y);
            As[lf4 * 4 + 2][r] = f2tf32(v.z);
            As[lf4 * 4 + 3][r] = f2tf32(v.w);
        }
        // load W chunk (32 k x 128 n), cvt tf32
        #pragma unroll
        for (int wp = 0; wp < 4; wp++) {
            int idx = tid + wp * 256;
            int kk = idx >> 5;
            int c4 = idx & 31;
            float4 w = *(const float4*)&W[(size_t)(k0 + kk) * 128 + c4 * 4];
            Ws[kk][c4 * 4 + 0] = f2tf32(w.x);
            Ws[kk][c4 * 4 + 1] = f2tf32(w.y);
            Ws[kk][c4 * 4 + 2] = f2tf32(w.z);
            Ws[kk][c4 * 4 + 3] = f2tf32(w.w);
        }
        __syncthreads();

        #pragma unroll
        for (int ks = 0; ks < KC / 8; ks++) {
            int kb = ks * 8;
            // B fragments (col-major k8 x n8): b0=(tg, g), b1=(tg+4, g)
            unsigned bf[8][2];
            #pragma unroll
            for (int nf = 0; nf < 8; nf++) {
                bf[nf][0] = Ws[kb + tg][wn + nf * 8 + g];
                bf[nf][1] = Ws[kb + tg + 4][wn + nf * 8 + g];
            }
            #pragma unroll
            for (int mf = 0; mf < 2; mf++) {
                int m0 = wm + mf * 16;
                // A fragments (row-major m16 x k8)
                unsigned a0 = As[kb + tg][m0 + g];
                unsigned a1 = As[kb + tg][m0 + g + 8];
                unsigned a2 = As[kb + tg + 4][m0 + g];
                unsigned a3 = As[kb + tg + 4][m0 + g + 8];
                #pragma unroll
                for (int nf = 0; nf < 8; nf++) {
                    asm volatile(
                        "mma.sync.aligned.m16n8k8.row.col.f32.tf32.tf32.f32 "
                        "{%0,%1,%2,%3}, {%4,%5,%6,%7}, {%8,%9}, {%0,%1,%2,%3};"
                        : "+f"(acc[mf][nf][0]), "+f"(acc[mf][nf][1]),
                          "+f"(acc[mf][nf][2]), "+f"(acc[mf][nf][3])
                        : "r"(a0), "r"(a1), "r"(a2), "r"(a3),
                          "r"(bf[nf][0]), "r"(bf[nf][1]));
                }
            }
        }
        __syncthreads();
    }

    // epilogue: c0=(g, 2tg), c1=(g, 2tg+1), c2=(g+8, 2tg), c3=(g+8, 2tg+1)
    #pragma unroll
    for (int mf = 0; mf < 2; mf++) {
        int r0 = row0 + wm + mf * 16 + g;
        int r1 = r0 + 8;
        float s0 = 1.f, s1 = 1.f;
        if (rowscale) {
            if (r0 < M) s0 = __ldg(&rowscale[r0]);
            if (r1 < M) s1 = __ldg(&rowscale[r1]);
        }
        #pragma unroll
        for (int nf = 0; nf < 8; nf++) {
            int c = wn + nf * 8 + 2 * tg;
            float bv0 = __ldg(&bias[c]);
            float bv1 = __ldg(&bias[c + 1]);
            if (r0 < M) {
                float2 o;
                o.x = fmaxf(acc[mf][nf][0] + bv0, 0.f) * s0;
                o.y = fmaxf(acc[mf][nf][1] + bv1, 0.f) * s0;
                *(float2*)&out[(size_t)r0 * 128 + c] = o;
            }
            if (r1 < M) {
                float2 o;
                o.x = fmaxf(acc[mf][nf][2] + bv0, 0.f) * s1;
                o.y = fmaxf(acc[mf][nf][3] + bv1, 0.f) * s1;
                *(float2*)&out[(size_t)r1 * 128 + c] = o;
            }
        }
    }
}

// ---------------- launcher ----------------
extern "C" void kernel_launch(void* const* d_in, const int* in_sizes, int n_in,
                              void* d_out, int out_size) {
    const int*   batch = (const int*)d_in[0];
    const int*   src   = (const int*)d_in[1];
    const int*   dst   = (const int*)d_in[2];
    const float* emb   = (const float*)d_in[3];
    const float* W1    = (const float*)d_in[4];
    const float* b1    = (const float*)d_in[5];
    const float* W2    = (const float*)d_in[6];
    const float* b2    = (const float*)d_in[7];
    const float* W3    = (const float*)d_in[8];
    const float* b3    = (const float*)d_in[9];
    float* out = (float*)d_out;

    float* H;   cudaGetSymbolAddress((void**)&H,   g_H);
    float* AGG; cudaGetSymbolAddress((void**)&AGG, g_AGG);
    float* NSRC; cudaGetSymbolAddress((void**)&NSRC, g_norm_src);

    const int TB = 256;
    // build CSR + norms
    zero_counts<<<(NNODES + TB - 1) / TB, TB>>>();
    hist_kernel<<<(NEDGES + TB - 1) / TB, TB>>>(src, dst);
    norm_kernel<<<(NNODES + TB - 1) / TB, TB>>>();
    deg_partial<<<NBLK_SCAN, 256>>>();
    scan_bsums<<<1, 256>>>();
    scan_apply<<<NBLK_SCAN, 256>>>();
    fill_kernel<<<(NEDGES + TB - 1) / TB, TB>>>(src, dst);

    // embedding gather (pre-scaled by norm_src)
    embed_kernel<<<(NNODES * 32 + TB - 1) / TB, TB>>>(batch, emb);

    int spmm_blocks = (NNODES * 32 + TB - 1) / TB;
    int gemm_blocks = (NNODES + 127) / 128;

    // layer 1  (H pre-scaled; gemm output pre-scaled for next spmm)
    spmm_kernel<<<spmm_blocks, TB>>>(H);
    gemm_tf32<<<gemm_blocks, 256>>>(AGG, W1, b1, H, NNODES, NSRC);
    // layer 2
    spmm_kernel<<<spmm_blocks, TB>>>(H);
    gemm_tf32<<<gemm_blocks, 256>>>(AGG, W2, b2, H, NNODES, NSRC);
    // layer 3 (final: no rowscale)
    spmm_kernel<<<spmm_blocks, TB>>>(H);
    gemm_tf32<<<gemm_blocks, 256>>>(AGG, W3, b3, out, NNODES, nullptr);
}